// round 1
// baseline (speedup 1.0000x reference)
#include <cuda_runtime.h>

// CTC greedy search, shapes fixed by the problem:
//   logits: (T=2048, N=32, V=1024) float32, batch_first = False
//   in_lens: (N,) int (int32 or int64 — detected at runtime)
// Outputs concatenated into d_out (float32):
//   [ max_total (N) | paths (T*N, layout t*N+n) | out_lens (N) ]

#define T_DIM 2048
#define N_DIM 32
#define V_DIM 1024
#define BLANK 1023   // (-1 + V) % V

// Scratch (allocation-free rule: __device__ globals). n-major for kernel2 coalescing.
__device__ int   g_amax[(size_t)T_DIM * N_DIM];
__device__ float g_maxv[(size_t)T_DIM * N_DIM];

// ---------------------------------------------------------------------------
// Kernel 1: one warp per (t, n) row of V=1024 logits.
// Computes argmax (first-occurrence tie-break), max logp = -log(sum exp(x-m)),
// writes scratch + the "default" paths values (masked_scatter leftover region).
// ---------------------------------------------------------------------------
__global__ void __launch_bounds__(256) ctc_rowmax_kernel(
    const float* __restrict__ logits, float* __restrict__ out_paths)
{
    const int warp_id = (blockIdx.x * 256 + threadIdx.x) >> 5;  // = t*N + n
    const int lane = threadIdx.x & 31;

    const float4* row =
        reinterpret_cast<const float4*>(logits) + (size_t)warp_id * (V_DIM / 4);

    float4 v[8];
#pragma unroll
    for (int k = 0; k < 8; k++) v[k] = row[lane + 32 * k];

    // per-lane max + first-occurrence argmax (indices visited in increasing order)
    float m = -1e30f; int mi = 0;
#pragma unroll
    for (int k = 0; k < 8; k++) {
        const int base = (lane + 32 * k) * 4;
        float x;
        x = v[k].x; if (x > m) { m = x; mi = base;     }
        x = v[k].y; if (x > m) { m = x; mi = base + 1; }
        x = v[k].z; if (x > m) { m = x; mi = base + 2; }
        x = v[k].w; if (x > m) { m = x; mi = base + 3; }
    }
    // warp reduce (ties -> smaller global index == first occurrence)
#pragma unroll
    for (int off = 16; off; off >>= 1) {
        float om = __shfl_down_sync(0xffffffffu, m, off);
        int  omi = __shfl_down_sync(0xffffffffu, mi, off);
        if (om > m || (om == m && omi < mi)) { m = om; mi = omi; }
    }
    m  = __shfl_sync(0xffffffffu, m, 0);
    mi = __shfl_sync(0xffffffffu, mi, 0);

    // sum exp(x - m); MUFU throughput (~2368 lane-ops/cyc chip) hides under HBM
    float s = 0.f;
#pragma unroll
    for (int k = 0; k < 8; k++) {
        s += __expf(v[k].x - m) + __expf(v[k].y - m)
           + __expf(v[k].z - m) + __expf(v[k].w - m);
    }
#pragma unroll
    for (int off = 16; off; off >>= 1) s += __shfl_down_sync(0xffffffffu, s, off);

    if (lane == 0) {
        const int t = warp_id / N_DIM;
        const int n = warp_id - t * N_DIM;
        g_amax[n * T_DIM + t] = mi;
        g_maxv[n * T_DIM + t] = -logf(s);      // max over V of log_softmax
        out_paths[warp_id] = (float)mi;        // default region: raw argmax
    }
}

// ---------------------------------------------------------------------------
// Kernel 2: one 256-thread block per batch row n.
//   * max_total[n] = sum_{t < L} maxlogp
//   * keep[t] = (a[t]!=blank) && (t==0 || a[t]!=a[t-1]) && (t<L)
//   * stream-compact kept tokens into paths[pos*N + n]; out_lens[n] = count
// ---------------------------------------------------------------------------
__global__ void __launch_bounds__(256) ctc_scan_kernel(
    const void* __restrict__ in_lens_raw, float* __restrict__ out)
{
    const int n    = blockIdx.x;
    const int tid  = threadIdx.x;
    const int lane = tid & 31;
    const int wid  = tid >> 5;

    // dtype-robust in_lens read: values are in [1, T] (never 0). If the buffer
    // is int64 (LE), every high 32-bit word is 0; if int32, word[1] >= 1.
    const int* w32 = (const int*)in_lens_raw;
    const bool is64 = (w32[1] == 0);
    const int L = is64 ? (int)((const long long*)in_lens_raw)[n] : w32[n];

    const int*   a  = g_amax + n * T_DIM;
    const float* mv = g_maxv + n * T_DIM;

    // ---- max_total ----
    float local = 0.f;
    for (int t = tid; t < T_DIM; t += 256)
        if (t < L) local += mv[t];
    __shared__ float red[8];
#pragma unroll
    for (int off = 16; off; off >>= 1)
        local += __shfl_down_sync(0xffffffffu, local, off);
    if (lane == 0) red[wid] = local;
    __syncthreads();
    if (tid == 0) {
        float tot = 0.f;
        for (int w = 0; w < 8; w++) tot += red[w];
        out[n] = tot;
    }

    // ---- dedup + stream compaction ----
    __shared__ int warp_counts[8];
    __shared__ int s_carry;
    if (tid == 0) s_carry = 0;
    __syncthreads();

    float* paths = out + N_DIM;

    for (int base = 0; base < T_DIM; base += 256) {
        const int t  = base + tid;
        const int av = a[t];
        const int prev = (t > 0) ? a[t - 1] : -123;  // t==0: no dedup condition
        const bool keep = (av != BLANK) && (av != prev) && (t < L);

        const unsigned mask = __ballot_sync(0xffffffffu, keep);
        if (lane == 0) warp_counts[wid] = __popc(mask);
        __syncthreads();                       // counts visible; s_carry stable

        int woff = 0;
        for (int w = 0; w < wid; w++) woff += warp_counts[w];
        if (keep) {
            const int pos = s_carry + woff + __popc(mask & ((1u << lane) - 1u));
            paths[pos * N_DIM + n] = (float)av;
        }
        __syncthreads();                       // all reads of s_carry done
        if (tid == 0) {
            int tot = 0;
            for (int w = 0; w < 8; w++) tot += warp_counts[w];
            s_carry += tot;
        }
        // next iteration's first __syncthreads orders this update before reads
    }

    __syncthreads();
    if (tid == 0) out[N_DIM + (size_t)T_DIM * N_DIM + n] = (float)s_carry;
}

// ---------------------------------------------------------------------------
extern "C" void kernel_launch(void* const* d_in, const int* in_sizes, int n_in,
                              void* d_out, int out_size)
{
    const float* logits = (const float*)d_in[0];
    const void*  lens   = d_in[1];
    float* out = (float*)d_out;

    (void)in_sizes; (void)n_in; (void)out_size;

    // Kernel 1: T*N = 65536 warps -> 8192 blocks of 256 threads
    ctc_rowmax_kernel<<<(T_DIM * N_DIM) / 8, 256>>>(logits, out + N_DIM);
    // Kernel 2: one block per batch row
    ctc_scan_kernel<<<N_DIM, 256>>>(lens, out);
}

// round 2
// speedup vs baseline: 1.1298x; 1.1298x over previous
#include <cuda_runtime.h>

// CTC greedy search, shapes fixed by the problem:
//   logits: (T=2048, N=32, V=1024) float32, batch_first = False
//   in_lens: (N,) int (int32 or int64 — detected at runtime)
// Outputs concatenated into d_out (float32):
//   [ max_total (N) | paths (T*N, layout t*N+n) | out_lens (N) ]

#define T_DIM 2048
#define N_DIM 32
#define V_DIM 1024
#define BLANK 1023   // (-1 + V) % V

// Scratch (allocation-free rule: __device__ globals). n-major for kernel2 coalescing.
__device__ int   g_amax[(size_t)T_DIM * N_DIM];
__device__ float g_maxv[(size_t)T_DIM * N_DIM];

// ---------------------------------------------------------------------------
// Kernel 1: one warp per (t, n) row of V=1024 logits.
// Computes argmax (first-occurrence tie-break), max logp = -log(sum exp(x-m)),
// writes scratch + the "default" paths values (masked_scatter leftover region).
// Memory-roofline bound: 268 MB @ ~6.8 TB/s.
// ---------------------------------------------------------------------------
__global__ void __launch_bounds__(256) ctc_rowmax_kernel(
    const float* __restrict__ logits, float* __restrict__ out_paths)
{
    const int warp_id = (blockIdx.x * 256 + threadIdx.x) >> 5;  // = t*N + n
    const int lane = threadIdx.x & 31;

    const float4* row =
        reinterpret_cast<const float4*>(logits) + (size_t)warp_id * (V_DIM / 4);

    float4 v[8];
#pragma unroll
    for (int k = 0; k < 8; k++) v[k] = row[lane + 32 * k];

    // per-lane max + first-occurrence argmax (indices visited in increasing order)
    float m = -1e30f; int mi = 0;
#pragma unroll
    for (int k = 0; k < 8; k++) {
        const int base = (lane + 32 * k) * 4;
        float x;
        x = v[k].x; if (x > m) { m = x; mi = base;     }
        x = v[k].y; if (x > m) { m = x; mi = base + 1; }
        x = v[k].z; if (x > m) { m = x; mi = base + 2; }
        x = v[k].w; if (x > m) { m = x; mi = base + 3; }
    }
    // warp reduce (ties -> smaller global index == first occurrence)
#pragma unroll
    for (int off = 16; off; off >>= 1) {
        float om = __shfl_down_sync(0xffffffffu, m, off);
        int  omi = __shfl_down_sync(0xffffffffu, mi, off);
        if (om > m || (om == m && omi < mi)) { m = om; mi = omi; }
    }
    m  = __shfl_sync(0xffffffffu, m, 0);
    mi = __shfl_sync(0xffffffffu, mi, 0);

    // sum exp(x - m); MUFU throughput hides under HBM stream
    float s = 0.f;
#pragma unroll
    for (int k = 0; k < 8; k++) {
        s += __expf(v[k].x - m) + __expf(v[k].y - m)
           + __expf(v[k].z - m) + __expf(v[k].w - m);
    }
#pragma unroll
    for (int off = 16; off; off >>= 1) s += __shfl_down_sync(0xffffffffu, s, off);

    if (lane == 0) {
        const int t = warp_id / N_DIM;
        const int n = warp_id - t * N_DIM;
        g_amax[n * T_DIM + t] = mi;
        g_maxv[n * T_DIM + t] = -logf(s);      // max over V of log_softmax
        out_paths[warp_id] = (float)mi;        // default region: raw argmax
    }
}

// ---------------------------------------------------------------------------
// Kernel 2 (single-pass): one 1024-thread block per batch row n.
// Each thread owns 2 consecutive timesteps (one int2 / float2 load).
//   * max_total[n] = sum_{t<L} maxlogp  (warp reduce + warp-0 reduce)
//   * keep flags -> one warp scan + one warp-0 scan of warp totals -> compaction
// Only 2 __syncthreads, no serialized carry loop.
// ---------------------------------------------------------------------------
__global__ void __launch_bounds__(1024) ctc_scan_kernel(
    const void* __restrict__ in_lens_raw, float* __restrict__ out)
{
    const int n    = blockIdx.x;
    const int tid  = threadIdx.x;     // 0..1023
    const int lane = tid & 31;
    const int wid  = tid >> 5;        // 0..31

    // dtype-robust in_lens read: values are in [1, T] (never 0). If the buffer
    // is int64 (LE), every high 32-bit word is 0; if int32, word[1] >= 1.
    const int* w32 = (const int*)in_lens_raw;
    const bool is64 = (w32[1] == 0);
    const int L = is64 ? (int)((const long long*)in_lens_raw)[n] : w32[n];

    const int*   a  = g_amax + n * T_DIM;
    const float* mv = g_maxv + n * T_DIM;

    // ---- single vector load of this thread's pair ----
    const int t0 = 2 * tid;
    const int2   aa = reinterpret_cast<const int2*>(a)[tid];
    const float2 mm = reinterpret_cast<const float2*>(mv)[tid];

    // prev element for t0: element t0-1 = previous thread's aa.y.
    int prev = __shfl_up_sync(0xffffffffu, aa.y, 1);
    if (lane == 0) prev = (tid == 0) ? -123 : a[t0 - 1];  // warp boundary / t=0

    const bool k0 = (aa.x != BLANK) && (aa.x != prev) && (t0     < L);
    const bool k1 = (aa.y != BLANK) && (aa.y != aa.x) && (t0 + 1 < L);
    const int  cnt = (int)k0 + (int)k1;

    // ---- max_total partial (fold into the same pass) ----
    float loc = ((t0 < L) ? mm.x : 0.f) + ((t0 + 1 < L) ? mm.y : 0.f);

    // ---- inclusive warp scan of cnt; warp reduce of loc ----
    int inc = cnt;
#pragma unroll
    for (int off = 1; off < 32; off <<= 1) {
        int v = __shfl_up_sync(0xffffffffu, inc, off);
        if (lane >= off) inc += v;
        loc += __shfl_down_sync(0xffffffffu, loc, off);  // butterfly-ish; lane0 valid
    }

    __shared__ int   s_wcnt[32];   // exclusive prefix of warp totals (after scan)
    __shared__ float s_wsum[32];
    if (lane == 31) s_wcnt[wid] = inc;      // warp total
    if (lane == 0)  s_wsum[wid] = loc;      // warp sum
    __syncthreads();

    if (wid == 0) {
        // scan 32 warp totals (exclusive), reduce 32 warp sums
        int v = s_wcnt[lane];
        int inc2 = v;
#pragma unroll
        for (int off = 1; off < 32; off <<= 1) {
            int u = __shfl_up_sync(0xffffffffu, inc2, off);
            if (lane >= off) inc2 += u;
        }
        s_wcnt[lane] = inc2 - v;            // exclusive warp offset

        float fs = s_wsum[lane];
#pragma unroll
        for (int off = 16; off; off >>= 1)
            fs += __shfl_down_sync(0xffffffffu, fs, off);

        if (lane == 31) out[N_DIM + (size_t)T_DIM * N_DIM + n] = (float)inc2;  // out_lens
        if (lane == 0)  out[n] = fs;                                           // max_total
    }
    __syncthreads();

    // ---- scatter kept tokens ----
    float* paths = out + N_DIM;
    int pos = s_wcnt[wid] + (inc - cnt);    // exclusive start for this thread
    if (k0) { paths[pos * N_DIM + n] = (float)aa.x; pos++; }
    if (k1) { paths[pos * N_DIM + n] = (float)aa.y; }
}

// ---------------------------------------------------------------------------
extern "C" void kernel_launch(void* const* d_in, const int* in_sizes, int n_in,
                              void* d_out, int out_size)
{
    const float* logits = (const float*)d_in[0];
    const void*  lens   = d_in[1];
    float* out = (float*)d_out;

    (void)in_sizes; (void)n_in; (void)out_size;

    // Kernel 1: T*N = 65536 warps -> 8192 blocks of 256 threads
    ctc_rowmax_kernel<<<(T_DIM * N_DIM) / 8, 256>>>(logits, out + N_DIM);
    // Kernel 2: one 1024-thread block per batch row, single pass
    ctc_scan_kernel<<<N_DIM, 1024>>>(lens, out);
}